// round 2
// baseline (speedup 1.0000x reference)
#include <cuda_runtime.h>

#define S     771     // STATE
#define NB    32      // batch
#define NT    128     // time
#define GRID  129     // CTAs (129*6 >= 771), co-resident on 152 SMs
#define NWARP 12
#define NTHR  (NWARP*32)
#define WJ    6       // output columns per CTA

// ---------------- persistent device state ----------------
__device__ float g_W[2][S*NB];          // scaled alphas, [state][batch], double buffered
__device__ float g_d[NT][NB];           // per-step per-batch sums of W (normalizers)
__device__ float g_m0[NB];              // initial max (log offset)
__device__ unsigned int g_count = 0;    // grid barrier
__device__ volatile unsigned int g_gen = 0;

__device__ __forceinline__ void gsync() {
    __threadfence();
    __syncthreads();
    if (threadIdx.x == 0) {
        unsigned my = g_gen;
        unsigned prev = atomicAdd(&g_count, 1u);
        if (prev == GRID - 1) {
            atomicExch(&g_count, 0u);
            __threadfence();
            g_gen = my + 1u;
        } else {
            while (g_gen == my) { }
            __threadfence();
        }
    }
    __syncthreads();
}

__global__ void __launch_bounds__(NTHR, 1)
crf_kernel(const float* __restrict__ em, const int* __restrict__ tags32,
           const float* __restrict__ mask, const float* __restrict__ trans,
           float* __restrict__ out)
{
    __shared__ __align__(16) float ET[WJ][772];       // exp(trans) column slice, [jc][i]
    __shared__ float s_part[NWARP][WJ][NB];
    __shared__ float s_outs[WJ][NB];
    __shared__ float s_red[NWARP];

    const int tid  = threadIdx.x;
    const int w    = tid >> 5;
    const int lane = tid & 31;         // lane == batch index
    const int cta  = blockIdx.x;
    const int j0   = cta * WJ;
    const int ncol = (S - j0 < WJ) ? (S - j0) : WJ;   // 6, last CTA gets 3

    // =============== INIT ===============
    for (int idx = tid; idx < WJ*772; idx += NTHR) (&ET[0][0])[idx] = 0.f;
    __syncthreads();
    for (int idx = tid; idx < ncol*S; idx += NTHR) {
        int jc = idx / S;
        int i  = idx - jc*S;
        ET[jc][i] = __expf(trans[i*S + (j0 + jc)]);   // exp(-1e9) -> 0 cleanly
    }
    // zero normalizer history for t>=1 (t=0 written directly below)
    for (int idx = cta*NTHR + tid + NB; idx < NT*NB; idx += GRID*NTHR)
        (&g_d[0][0])[idx] = 0.f;

    if (cta < NB) {   // CTA b builds W_0 for batch b
        const int b = cta;
        const float* em0 = em + (size_t)b*NT*S;
        float mx = -3.0e38f;
        for (int j = tid; j < S; j += NTHR)
            mx = fmaxf(mx, trans[j] + em0[j]);          // trans[BOS=0][j]
        #pragma unroll
        for (int o = 16; o; o >>= 1) mx = fmaxf(mx, __shfl_xor_sync(0xffffffffu, mx, o));
        if (lane == 0) s_red[w] = mx;
        __syncthreads();
        mx = s_red[0];
        #pragma unroll
        for (int k = 1; k < NWARP; k++) mx = fmaxf(mx, s_red[k]);

        float sm = 0.f;
        for (int j = tid; j < S; j += NTHR) {
            float v = __expf(trans[j] + em0[j] - mx);
            g_W[0][j*NB + b] = v;
            sm += v;
        }
        #pragma unroll
        for (int o = 16; o; o >>= 1) sm += __shfl_xor_sync(0xffffffffu, sm, o);
        __syncthreads();
        if (lane == 0) s_red[w] = sm;
        __syncthreads();
        if (tid == 0) {
            float tot = 0.f;
            #pragma unroll
            for (int k = 0; k < NWARP; k++) tot += s_red[k];
            g_d[0][b] = tot;
            g_m0[b]  = mx;
        }
    }
    gsync();

    // =============== MAIN LOOP: 127 matvec steps ===============
    for (int t = 1; t < NT; ++t) {
        const float* __restrict__ Wp = g_W[(t-1) & 1];
        float*       __restrict__ Wc = g_W[t & 1];

        // prefetch per-lane(b) scalars (pure latency, off critical path)
        float invd = __fdividef(1.f, __ldcg(&g_d[t-1][lane]));
        float mk   = mask[lane*NT + t];
        float eme = 0.f, oldv = 0.f;
        if (w < ncol) {
            int j = j0 + w;
            eme  = __expf(em[(size_t)lane*NT*S + (size_t)t*S + j]);
            oldv = __ldcg(&Wp[j*NB + lane]);
        }

        float acc[WJ];
        #pragma unroll
        for (int jc = 0; jc < WJ; jc++) acc[jc] = 0.f;

        // i-dimension split across 12 warps in 4-aligned blocks (float4 ET loads)
        for (int bi = w; bi < (S >> 2); bi += NWARP) {
            int i = bi << 2;
            float u0 = __ldcg(&Wp[(i+0)*NB + lane]);
            float u1 = __ldcg(&Wp[(i+1)*NB + lane]);
            float u2 = __ldcg(&Wp[(i+2)*NB + lane]);
            float u3 = __ldcg(&Wp[(i+3)*NB + lane]);
            #pragma unroll
            for (int jc = 0; jc < WJ; jc++) {
                float4 e = *reinterpret_cast<const float4*>(&ET[jc][i]);
                float a = acc[jc];
                a = fmaf(u0, e.x, a);
                a = fmaf(u1, e.y, a);
                a = fmaf(u2, e.z, a);
                a = fmaf(u3, e.w, a);
                acc[jc] = a;
            }
        }
        if (w == 0) {   // tail i = 768..770
            #pragma unroll
            for (int i = (S & ~3); i < S; ++i) {
                float u = __ldcg(&Wp[i*NB + lane]);
                #pragma unroll
                for (int jc = 0; jc < WJ; jc++) acc[jc] = fmaf(u, ET[jc][i], acc[jc]);
            }
        }

        #pragma unroll
        for (int jc = 0; jc < WJ; jc++) s_part[w][jc][lane] = acc[jc];
        __syncthreads();

        if (w < WJ) {
            float ssum = 0.f;
            #pragma unroll
            for (int ww = 0; ww < NWARP; ww++) ssum += s_part[ww][w][lane];
            float nv = 0.f;
            if (w < ncol) {
                nv = (mk > 0.f) ? (ssum * invd * eme) : oldv;   // masked step: carry old
                Wc[(j0 + w)*NB + lane] = nv;
            }
            s_outs[w][lane] = nv;
        }
        __syncthreads();
        if (w == 0) {   // per-CTA partial of d_t[b], one atomic per (CTA,b)
            float dsum = 0.f;
            #pragma unroll
            for (int jc = 0; jc < WJ; jc++) dsum += s_outs[jc][lane];
            atomicAdd(&g_d[t][lane], dsum);
        }
        gsync();
    }

    // =============== FINAL: scores, log_z, NLL (CTA 0) ===============
    if (cta == 0) {
        const bool is64 = (tags32[1] == 0);   // int64 tags have zero high words
        float sc = 0.f, ld = 0.f;
        int tlo = 1 + w*11;
        int thi = (tlo + 11 < NT) ? (tlo + 11) : NT;
        for (int t = tlo; t < thi; ++t) {
            float m = mask[lane*NT + t];
            int cur = is64 ? tags32[(lane*NT + t)*2]     : tags32[lane*NT + t];
            int prv = is64 ? tags32[(lane*NT + t - 1)*2] : tags32[lane*NT + t - 1];
            sc += (em[(size_t)lane*NT*S + (size_t)t*S + cur] + trans[prv*S + cur]) * m;
            if (m > 0.f) ld += logf(__ldcg(&g_d[t-1][lane]));
        }
        s_part[w][0][lane] = sc;
        s_part[w][1][lane] = ld;
        __syncthreads();
        if (w == 0) {
            const int b = lane;
            float score = 0.f, L = 0.f;
            #pragma unroll
            for (int ww = 0; ww < NWARP; ww++) { score += s_part[ww][0][lane]; L += s_part[ww][1][lane]; }
            int tag0 = is64 ? tags32[(b*NT)*2] : tags32[b*NT];
            score += trans[tag0] + em[(size_t)b*NT*S + tag0];    // trans[BOS=0][tag0]
            float msum = 0.f;
            for (int t = 0; t < NT; t++) msum += mask[b*NT + t];
            int lastidx = (int)msum - 1;
            int lasttag = is64 ? tags32[(b*NT + lastidx)*2] : tags32[b*NT + lastidx];
            score += trans[lasttag*S + 1];                       // trans[last, EOS=1]
            L += __ldcg(&g_m0[b]);
            float zs = 0.f;
            for (int j = 0; j < S; j++)
                zs += __ldcg(&g_W[1][j*NB + b]) * __expf(trans[j*S + 1]);  // (NT-1)&1 == 1
            float r = (L + logf(zs)) - score;   // log_z - score
            #pragma unroll
            for (int o = 16; o; o >>= 1) r += __shfl_xor_sync(0xffffffffu, r, o);
            if (lane == 0) out[0] = r;          // NLL = sum_b (log_z - score)
        }
    }
}

extern "C" void kernel_launch(void* const* d_in, const int* in_sizes, int n_in,
                              void* d_out, int out_size)
{
    (void)in_sizes; (void)n_in; (void)out_size;
    const float* em    = (const float*)d_in[0];
    const int*   tags  = (const int*)  d_in[1];   // int64 or int32, detected in-kernel
    const float* mask  = (const float*)d_in[2];
    const float* trans = (const float*)d_in[3];
    float* out = (float*)d_out;
    crf_kernel<<<GRID, NTHR>>>(em, tags, mask, trans, out);
}